// round 12
// baseline (speedup 1.0000x reference)
#include <cuda_runtime.h>
#include <cuda_bf16.h>
#include <cstdint>

// Closed-form per-(batch,class) reduction of the symmetric-pair loss.
// For a group of n points of one symmetric class (c in {0,1,2}), with
// u_i = x_i - CENTER_X:
//   sum_{i<j} (u_i+u_j)^2 = (n-2)*Sum(u^2) + (Sum u)^2
//   sum_{i<j} (y_i-y_j)^2 =  n   *Sum(y^2) - (Sum y)^2
//   #pairs                =  n(n-1)/2
// Both identities are exactly 0 for n in {0,1}.
//
// SINGLE kernel. Each CTA packs its (loss, count) into ONE u64
// fixed-point word:  packed = (round(loss * 2^11) << 26) | count.
//   count  <= 256*C(512,2) = 33.49M < 2^26  (no carry into loss field)
//   loss   <= 2 * pairs  -> loss_fx < 2^38  (packed sum < 2^64)
// Integer addition is order-invariant -> bit-deterministic result.
// Completion detection: one acq_rel ticket atomic (release orders the
// value atomic; acquire makes all contributions visible to the last CTA).

#define CENTER_X 0.5f
#define BATCH 256
#define NPTS  512
#define LOSS_SCALE 2048.0        // 2^11
#define CNT_BITS   26
#define CNT_MASK   ((1ull << CNT_BITS) - 1ull)

__device__ unsigned long long g_pack   = 0;  // (loss_fx << 26) | count
__device__ unsigned int       g_ticket = 0;  // completion ticket

__device__ __forceinline__ unsigned long long ld_acq_u64(unsigned long long* p) {
    unsigned long long v;
    asm volatile("ld.global.acquire.gpu.b64 %0, [%1];" : "=l"(v) : "l"(p) : "memory");
    return v;
}

__device__ __forceinline__ unsigned int atom_add_acq_rel_u32(unsigned int* p,
                                                             unsigned int v) {
    unsigned int old;
    asm volatile("atom.add.acq_rel.gpu.u32 %0, [%1], %2;"
                 : "=r"(old) : "l"(p), "r"(v) : "memory");
    return old;
}

__global__ void __launch_bounds__(256) sym_fused(const float* __restrict__ kp,
                                                 const int* __restrict__ cls,
                                                 float* __restrict__ out) {
    const int b = blockIdx.x;
    const int t = threadIdx.x;

    // Each thread handles 2 consecutive points: 1x float4 + 1x int2.
    const float4 p = reinterpret_cast<const float4*>(kp)[(size_t)b * 256 + t];
    const int2   c = reinterpret_cast<const int2*>(cls)[(size_t)b * 256 + t];

    float acc[12];  // [class][su, su2, sy, sy2]
#pragma unroll
    for (int k = 0; k < 12; k++) acc[k] = 0.0f;

    const float ux[2] = {p.x - CENTER_X, p.z - CENTER_X};
    const float yy[2] = {p.y, p.w};
    const int   cc[2] = {c.x, c.y};
    int wcnt[3];  // warp-level class counts via ballot (uniform across lanes)
#pragma unroll
    for (int k = 0; k < 3; k++) {
        const unsigned m0 = __ballot_sync(0xffffffffu, cc[0] == k);
        const unsigned m1 = __ballot_sync(0xffffffffu, cc[1] == k);
        wcnt[k] = __popc(m0) + __popc(m1);
    }
#pragma unroll
    for (int j = 0; j < 2; j++) {
#pragma unroll
        for (int k = 0; k < 3; k++) {
            if (cc[j] == k) {
                acc[k * 4 + 0] += ux[j];
                acc[k * 4 + 1]  = fmaf(ux[j], ux[j], acc[k * 4 + 1]);
                acc[k * 4 + 2] += yy[j];
                acc[k * 4 + 3]  = fmaf(yy[j], yy[j], acc[k * 4 + 3]);
            }
        }
    }

    // Intra-warp reduction (shuffles): 12 float accumulators.
#pragma unroll
    for (int off = 16; off > 0; off >>= 1) {
#pragma unroll
        for (int k = 0; k < 12; k++)
            acc[k] += __shfl_down_sync(0xffffffffu, acc[k], off);
    }

    // Cross-warp via shared memory (8 warps publish 12 sums + 3 counts).
    __shared__ float sf[8][16];  // padded row
    __shared__ float stot[16];
    const int wid = t >> 5, lid = t & 31;
    if (lid == 0) {
#pragma unroll
        for (int k = 0; k < 12; k++) sf[wid][k] = acc[k];
#pragma unroll
        for (int k = 0; k < 3; k++)  sf[wid][12 + k] = (float)wcnt[k];
    }
    __syncthreads();

    // Warp 0, lanes 0..14: each lane sums one accumulator across 8 warps.
    if (wid == 0) {
        if (lid < 15) {
            float s = 0.0f;
#pragma unroll
            for (int w = 0; w < 8; w++) s += sf[w][lid];
            stot[lid] = s;
        }
        __syncwarp();
        if (lid == 0) {
            float loss = 0.0f, count = 0.0f;
#pragma unroll
            for (int k = 0; k < 3; k++) {
                const float SU  = stot[k * 4 + 0];
                const float SU2 = stot[k * 4 + 1];
                const float SY  = stot[k * 4 + 2];
                const float SY2 = stot[k * 4 + 3];
                const float n   = stot[12 + k];
                loss  += (n - 2.0f) * SU2 + SU * SU + n * SY2 - SY * SY;
                count += n * (n - 1.0f) * 0.5f;
            }
            // One packed deterministic fixed-point atomic.
            const unsigned long long lfx =
                (unsigned long long)llrint((double)loss * LOSS_SCALE);
            const unsigned long long cu =
                (unsigned long long)llrintf(count);  // exact integer
            atomicAdd(&g_pack, (lfx << CNT_BITS) | cu);

            // acq_rel ticket: releases the value atomic above; the last
            // observer's acquire makes all 256 contributions visible.
            const unsigned int v = atom_add_acq_rel_u32(&g_ticket, 1u);
            if (v == (unsigned int)(BATCH - 1)) {
                const unsigned long long P = ld_acq_u64(&g_pack);
                const double loss_d = (double)(P >> CNT_BITS) / LOSS_SCALE;
                const unsigned long long C = P & CNT_MASK;
                const double cnt_d = (C < 1ull) ? 1.0 : (double)C;
                out[0] = (float)(loss_d / cnt_d);
                // Reset for the next graph replay (deterministic).
                g_pack   = 0ull;
                g_ticket = 0u;
            }
        }
    }
}

extern "C" void kernel_launch(void* const* d_in, const int* in_sizes, int n_in,
                              void* d_out, int out_size) {
    const float* kp  = (const float*)d_in[0];  // [256, 512, 2] f32
    const int*   cls = (const int*)d_in[1];    // [256, 512] i32
    float* out = (float*)d_out;

    sym_fused<<<BATCH, 256>>>(kp, cls, out);
}

// round 13
// speedup vs baseline: 1.0071x; 1.0071x over previous
#include <cuda_runtime.h>
#include <cuda_bf16.h>
#include <cstdint>

// Closed-form per-(batch,class) reduction of the symmetric-pair loss.
// For a group of n points of one symmetric class (c in {0,1,2}), with
// u_i = x_i - CENTER_X:
//   sum_{i<j} (u_i+u_j)^2 = (n-2)*Sum(u^2) + (Sum u)^2
//   sum_{i<j} (y_i-y_j)^2 =  n   *Sum(y^2) - (Sum y)^2
//   #pairs                =  n(n-1)/2
// Both identities are exactly 0 for n in {0,1}.
//
// SINGLE kernel, SINGLE atomic: each CTA adds one packed u64
//   packed = (1 << 55) | (round(loss * 8) << 25) | count
// Field bounds (worst case over any input):
//   count  <= 256*C(512,2) = 33,488,896 < 2^25            -> bits [24:0]
//   loss*8 <= 2*33.49M*8 + rounding      < 2^30            -> bits [54:25]
//   ticket sum = 256                     < 2^9             -> bits [63:55]
// No field can carry into the next; integer addition is order-invariant
// -> bit-deterministic. The CTA whose returned 'old' has ticket==255 is
// last and ALREADY holds the grand total as old + its own packed value:
// no second atomic, no acquire re-read on the serial tail.

#define CENTER_X 0.5f
#define BATCH 256
#define NPTS  512
#define LOSS_SCALE 8.0           // 2^3
#define CNT_BITS   25
#define CNT_MASK   ((1ull << CNT_BITS) - 1ull)
#define LOSS_MASK  ((1ull << 30) - 1ull)
#define TICKET_SHIFT 55

__device__ unsigned long long g_pack = 0;  // ticket | loss_fx | count

__global__ void __launch_bounds__(256) sym_fused(const float* __restrict__ kp,
                                                 const int* __restrict__ cls,
                                                 float* __restrict__ out) {
    const int b = blockIdx.x;
    const int t = threadIdx.x;

    // Each thread handles 2 consecutive points: 1x float4 + 1x int2.
    const float4 p = reinterpret_cast<const float4*>(kp)[(size_t)b * 256 + t];
    const int2   c = reinterpret_cast<const int2*>(cls)[(size_t)b * 256 + t];

    float acc[12];  // [class][su, su2, sy, sy2]
#pragma unroll
    for (int k = 0; k < 12; k++) acc[k] = 0.0f;

    const float ux[2] = {p.x - CENTER_X, p.z - CENTER_X};
    const float yy[2] = {p.y, p.w};
    const int   cc[2] = {c.x, c.y};
    int wcnt[3];  // warp-level class counts via ballot (uniform across lanes)
#pragma unroll
    for (int k = 0; k < 3; k++) {
        const unsigned m0 = __ballot_sync(0xffffffffu, cc[0] == k);
        const unsigned m1 = __ballot_sync(0xffffffffu, cc[1] == k);
        wcnt[k] = __popc(m0) + __popc(m1);
    }
#pragma unroll
    for (int j = 0; j < 2; j++) {
#pragma unroll
        for (int k = 0; k < 3; k++) {
            if (cc[j] == k) {
                acc[k * 4 + 0] += ux[j];
                acc[k * 4 + 1]  = fmaf(ux[j], ux[j], acc[k * 4 + 1]);
                acc[k * 4 + 2] += yy[j];
                acc[k * 4 + 3]  = fmaf(yy[j], yy[j], acc[k * 4 + 3]);
            }
        }
    }

    // Intra-warp reduction (shuffles): 12 float accumulators.
#pragma unroll
    for (int off = 16; off > 0; off >>= 1) {
#pragma unroll
        for (int k = 0; k < 12; k++)
            acc[k] += __shfl_down_sync(0xffffffffu, acc[k], off);
    }

    // Cross-warp via shared memory (8 warps publish 12 sums + 3 counts).
    __shared__ float sf[8][16];  // padded row
    __shared__ float stot[16];
    const int wid = t >> 5, lid = t & 31;
    if (lid == 0) {
#pragma unroll
        for (int k = 0; k < 12; k++) sf[wid][k] = acc[k];
#pragma unroll
        for (int k = 0; k < 3; k++)  sf[wid][12 + k] = (float)wcnt[k];
    }
    __syncthreads();

    // Warp 0, lanes 0..14: each lane sums one accumulator across 8 warps.
    if (wid == 0) {
        if (lid < 15) {
            float s = 0.0f;
#pragma unroll
            for (int w = 0; w < 8; w++) s += sf[w][lid];
            stot[lid] = s;
        }
        __syncwarp();
        if (lid == 0) {
            float loss = 0.0f, count = 0.0f;
#pragma unroll
            for (int k = 0; k < 3; k++) {
                const float SU  = stot[k * 4 + 0];
                const float SU2 = stot[k * 4 + 1];
                const float SY  = stot[k * 4 + 2];
                const float SY2 = stot[k * 4 + 3];
                const float n   = stot[12 + k];
                loss  += (n - 2.0f) * SU2 + SU * SU + n * SY2 - SY * SY;
                count += n * (n - 1.0f) * 0.5f;
            }
            // ONE packed deterministic atomic; return value doubles as
            // completion detection AND carries the grand total.
            const unsigned long long lfx =
                (unsigned long long)llrint((double)loss * LOSS_SCALE);
            const unsigned long long cu =
                (unsigned long long)llrintf(count);  // exact integer
            const unsigned long long mine =
                (1ull << TICKET_SHIFT) | (lfx << CNT_BITS) | cu;
            const unsigned long long old = atomicAdd(&g_pack, mine);

            if ((old >> TICKET_SHIFT) == (unsigned long long)(BATCH - 1)) {
                const unsigned long long total = old + mine;
                const double loss_d =
                    (double)((total >> CNT_BITS) & LOSS_MASK) / LOSS_SCALE;
                const unsigned long long C = total & CNT_MASK;
                const double cnt_d = (C < 1ull) ? 1.0 : (double)C;
                out[0] = (float)(loss_d / cnt_d);
                g_pack = 0ull;  // reset for next graph replay (deterministic)
            }
        }
    }
}

extern "C" void kernel_launch(void* const* d_in, const int* in_sizes, int n_in,
                              void* d_out, int out_size) {
    const float* kp  = (const float*)d_in[0];  // [256, 512, 2] f32
    const int*   cls = (const int*)d_in[1];    // [256, 512] i32
    float* out = (float*)d_out;

    sym_fused<<<BATCH, 256>>>(kp, cls, out);
}

// round 14
// speedup vs baseline: 1.0406x; 1.0332x over previous
#include <cuda_runtime.h>
#include <cuda_bf16.h>
#include <cstdint>

// Closed-form per-(batch,class) reduction of the symmetric-pair loss.
// For a group of n points of one symmetric class (c in {0,1,2}), with
// u_i = x_i - CENTER_X:
//   sum_{i<j} (u_i+u_j)^2 = (n-2)*Sum(u^2) + (Sum u)^2
//   sum_{i<j} (y_i-y_j)^2 =  n   *Sum(y^2) - (Sum y)^2
//   #pairs                =  n(n-1)/2
// Both identities are exactly 0 for n in {0,1}.
//
// SINGLE kernel, SINGLE atomic (R13 finalize):
//   packed = (1 << 55) | (round(loss * 8) << 25) | count
//   count  <= 256*C(512,2) = 33,488,896 < 2^25   -> bits [24:0]
//   loss*8 < 2^30                                 -> bits [54:25]
//   ticket sum = 256 < 2^9                        -> bits [63:55]
// Integer addition is order-invariant -> deterministic. The CTA whose
// returned 'old' shows ticket==255 already holds the grand total.
//
// R14 shape probe: 256 CTAs x 128 threads, 4 points/thread
// (2x float4 + 1x int4 batched loads), 4-warp cross-warp stage.

#define CENTER_X 0.5f
#define BATCH 256
#define NPTS  512
#define TPB   128
#define LOSS_SCALE 8.0           // 2^3
#define CNT_BITS   25
#define CNT_MASK   ((1ull << CNT_BITS) - 1ull)
#define LOSS_MASK  ((1ull << 30) - 1ull)
#define TICKET_SHIFT 55

__device__ unsigned long long g_pack = 0;  // ticket | loss_fx | count

__global__ void __launch_bounds__(TPB) sym_fused(const float* __restrict__ kp,
                                                 const int* __restrict__ cls,
                                                 float* __restrict__ out) {
    const int b = blockIdx.x;
    const int t = threadIdx.x;

    // Each thread handles 4 consecutive points: 2x float4 + 1x int4.
    const float4* kp4 = reinterpret_cast<const float4*>(kp) + (size_t)b * 256;
    const float4 pA = kp4[2 * t];          // points 4t, 4t+1
    const float4 pB = kp4[2 * t + 1];      // points 4t+2, 4t+3
    const int4   c4 = reinterpret_cast<const int4*>(cls)[(size_t)b * 128 + t];

    float acc[12];  // [class][su, su2, sy, sy2]
#pragma unroll
    for (int k = 0; k < 12; k++) acc[k] = 0.0f;

    const float ux[4] = {pA.x - CENTER_X, pA.z - CENTER_X,
                         pB.x - CENTER_X, pB.z - CENTER_X};
    const float yy[4] = {pA.y, pA.w, pB.y, pB.w};
    const int   cc[4] = {c4.x, c4.y, c4.z, c4.w};

    int wcnt[3];  // warp-level class counts via ballot (uniform across lanes)
#pragma unroll
    for (int k = 0; k < 3; k++) {
        int n = 0;
#pragma unroll
        for (int j = 0; j < 4; j++)
            n += __popc(__ballot_sync(0xffffffffu, cc[j] == k));
        wcnt[k] = n;
    }

#pragma unroll
    for (int j = 0; j < 4; j++) {
#pragma unroll
        for (int k = 0; k < 3; k++) {
            if (cc[j] == k) {
                acc[k * 4 + 0] += ux[j];
                acc[k * 4 + 1]  = fmaf(ux[j], ux[j], acc[k * 4 + 1]);
                acc[k * 4 + 2] += yy[j];
                acc[k * 4 + 3]  = fmaf(yy[j], yy[j], acc[k * 4 + 3]);
            }
        }
    }

    // Intra-warp reduction (shuffles): 12 float accumulators.
#pragma unroll
    for (int off = 16; off > 0; off >>= 1) {
#pragma unroll
        for (int k = 0; k < 12; k++)
            acc[k] += __shfl_down_sync(0xffffffffu, acc[k], off);
    }

    // Cross-warp via shared memory (4 warps publish 12 sums + 3 counts).
    __shared__ float sf[4][16];  // padded row
    __shared__ float stot[16];
    const int wid = t >> 5, lid = t & 31;
    if (lid == 0) {
#pragma unroll
        for (int k = 0; k < 12; k++) sf[wid][k] = acc[k];
#pragma unroll
        for (int k = 0; k < 3; k++)  sf[wid][12 + k] = (float)wcnt[k];
    }
    __syncthreads();

    // Warp 0, lanes 0..14: each lane sums one accumulator across 4 warps.
    if (wid == 0) {
        if (lid < 15) {
            float s = 0.0f;
#pragma unroll
            for (int w = 0; w < 4; w++) s += sf[w][lid];
            stot[lid] = s;
        }
        __syncwarp();
        if (lid == 0) {
            float loss = 0.0f, count = 0.0f;
#pragma unroll
            for (int k = 0; k < 3; k++) {
                const float SU  = stot[k * 4 + 0];
                const float SU2 = stot[k * 4 + 1];
                const float SY  = stot[k * 4 + 2];
                const float SY2 = stot[k * 4 + 3];
                const float n   = stot[12 + k];
                loss  += (n - 2.0f) * SU2 + SU * SU + n * SY2 - SY * SY;
                count += n * (n - 1.0f) * 0.5f;
            }
            // ONE packed deterministic atomic; return value doubles as
            // completion detection AND carries the grand total.
            const unsigned long long lfx =
                (unsigned long long)llrint((double)loss * LOSS_SCALE);
            const unsigned long long cu =
                (unsigned long long)llrintf(count);  // exact integer
            const unsigned long long mine =
                (1ull << TICKET_SHIFT) | (lfx << CNT_BITS) | cu;
            const unsigned long long old = atomicAdd(&g_pack, mine);

            if ((old >> TICKET_SHIFT) == (unsigned long long)(BATCH - 1)) {
                const unsigned long long total = old + mine;
                const double loss_d =
                    (double)((total >> CNT_BITS) & LOSS_MASK) / LOSS_SCALE;
                const unsigned long long C = total & CNT_MASK;
                const double cnt_d = (C < 1ull) ? 1.0 : (double)C;
                out[0] = (float)(loss_d / cnt_d);
                g_pack = 0ull;  // reset for next graph replay (deterministic)
            }
        }
    }
}

extern "C" void kernel_launch(void* const* d_in, const int* in_sizes, int n_in,
                              void* d_out, int out_size) {
    const float* kp  = (const float*)d_in[0];  // [256, 512, 2] f32
    const int*   cls = (const int*)d_in[1];    // [256, 512] i32
    float* out = (float*)d_out;

    sym_fused<<<BATCH, TPB>>>(kp, cls, out);
}